// round 1
// baseline (speedup 1.0000x reference)
#include <cuda_runtime.h>
#include <cstdint>

#define NA 100000
#define NB 100000
#define IN_DIM 256
#define OUT_DIM 256
#define NE 320000
#define LN_EPS 1e-5f

// ---------------- scratch (device globals; no allocation allowed) -----------
// proj: [NB][512]  (cols 0..255 = path0 projection, 256..511 = path1)
__device__ float g_proj[(size_t)NB * 512];
// agg:  [2][NA][256]
__device__ float g_agg[(size_t)2 * NA * 256];
// cnt:  [2][NA]
__device__ float g_cnt[2 * NA];

// ---------------- f32x2 packed helpers (sm_100+: FFMA2 double-rate) ---------
__device__ __forceinline__ unsigned long long pack2(float lo, float hi) {
    unsigned long long p;
    asm("mov.b64 %0, {%1, %2};" : "=l"(p) : "f"(lo), "f"(hi));
    return p;
}
__device__ __forceinline__ void unpack2(unsigned long long p, float& lo, float& hi) {
    asm("mov.b64 {%0, %1}, %2;" : "=f"(lo), "=f"(hi) : "l"(p));
}
__device__ __forceinline__ unsigned long long fma2(unsigned long long a,
                                                   unsigned long long b,
                                                   unsigned long long c) {
    unsigned long long d;
    asm("fma.rn.f32x2 %0, %1, %2, %3;" : "=l"(d) : "l"(a), "l"(b), "l"(c));
    return d;
}

// ---------------- zero kernels ---------------------------------------------
__global__ __launch_bounds__(256) void zero_scratch_kernel() {
    size_t i = (size_t)blockIdx.x * 256 + threadIdx.x;
    const size_t n4_agg = (size_t)2 * NA * 256 / 4;   // 12,800,000 float4
    const size_t n4_cnt = (size_t)2 * NA / 4;         // 50,000 float4
    float4 z = make_float4(0.f, 0.f, 0.f, 0.f);
    if (i < n4_agg) {
        reinterpret_cast<float4*>(g_agg)[i] = z;
    } else {
        size_t j = i - n4_agg;
        if (j < n4_cnt) reinterpret_cast<float4*>(g_cnt)[j] = z;
    }
}

__global__ __launch_bounds__(256) void zero_outB_kernel(float* __restrict__ outB) {
    size_t i = (size_t)blockIdx.x * 256 + threadIdx.x;
    const size_t n4 = (size_t)NB * OUT_DIM / 4;       // 6,400,000 float4
    if (i < n4)
        reinterpret_cast<float4*>(outB)[i] = make_float4(0.f, 0.f, 0.f, 0.f);
}

// ---------------- dual GEMM: proj = X @ [W0 | W1] + [b0 | b1] ---------------
// Block tile 128x128, BK=16, 256 threads, thread tile 8x8 held as f32x2 pairs.
// grid = (ceil(NB/128), 4); bn in {0,1} -> W0 cols {0..127, 128..255},
//                           bn in {2,3} -> W1.
__global__ __launch_bounds__(256) void gemm_dual_kernel(
    const float* __restrict__ X,
    const float* __restrict__ W0, const float* __restrict__ b0,
    const float* __restrict__ W1, const float* __restrict__ b1)
{
    __shared__ float Xs[16][128 + 4];
    __shared__ float Ws[16][128];

    const int bm = blockIdx.x;
    const int bn = blockIdx.y;
    const float* __restrict__ W    = (bn < 2) ? W0 : W1;
    const float* __restrict__ bias = (bn < 2) ? b0 : b1;
    const int wcol = (bn & 1) * 128;       // column offset inside this W
    const int m0 = bm * 128;

    const int tid = threadIdx.x;
    const int tx = tid & 15;               // 0..15
    const int ty = tid >> 4;               // 0..15
    const int rowBase = ty * 8;

    unsigned long long acc[8][4];
#pragma unroll
    for (int i = 0; i < 8; i++)
#pragma unroll
        for (int j = 0; j < 4; j++) acc[i][j] = 0ull;

    for (int k0 = 0; k0 < IN_DIM; k0 += 16) {
        // ---- load X tile (128 rows x 16 cols), store transposed -----------
#pragma unroll
        for (int l = 0; l < 2; l++) {
            int lin = tid + l * 256;
            int r  = lin >> 2;             // 0..127
            int c4 = lin & 3;              // 0..3  (x4 floats)
            int grow = m0 + r;
            float4 v = make_float4(0.f, 0.f, 0.f, 0.f);
            if (grow < NB)
                v = *reinterpret_cast<const float4*>(X + (size_t)grow * IN_DIM + k0 + c4 * 4);
            Xs[c4 * 4 + 0][r] = v.x;
            Xs[c4 * 4 + 1][r] = v.y;
            Xs[c4 * 4 + 2][r] = v.z;
            Xs[c4 * 4 + 3][r] = v.w;
        }
        // ---- load W tile (16 rows x 128 cols) -----------------------------
#pragma unroll
        for (int l = 0; l < 2; l++) {
            int lin = tid + l * 256;
            int r  = lin >> 5;             // 0..15
            int c4 = lin & 31;             // 0..31 (x4 floats)
            float4 v = *reinterpret_cast<const float4*>(W + (size_t)(k0 + r) * OUT_DIM + wcol + c4 * 4);
            *reinterpret_cast<float4*>(&Ws[r][c4 * 4]) = v;
        }
        __syncthreads();

#pragma unroll
        for (int k = 0; k < 16; k++) {
            unsigned long long bp[4];
#pragma unroll
            for (int j = 0; j < 4; j++) {
                // column pairs at tx*2 + j*32 : conflict-free LDS.64
                float2 b2 = *reinterpret_cast<const float2*>(&Ws[k][tx * 2 + j * 32]);
                bp[j] = pack2(b2.x, b2.y);
            }
#pragma unroll
            for (int i = 0; i < 8; i++) {
                float a = Xs[k][rowBase + i];
                unsigned long long ap = pack2(a, a);
#pragma unroll
                for (int j = 0; j < 4; j++) acc[i][j] = fma2(ap, bp[j], acc[i][j]);
            }
        }
        __syncthreads();
    }

    // ---- epilogue: add bias, store to g_proj -------------------------------
#pragma unroll
    for (int i = 0; i < 8; i++) {
        int grow = m0 + rowBase + i;
        if (grow >= NB) continue;
        float* outp = g_proj + (size_t)grow * 512 + bn * 128;
#pragma unroll
        for (int j = 0; j < 4; j++) {
            int c = tx * 2 + j * 32;
            float lo, hi;
            unpack2(acc[i][j], lo, hi);
            lo += bias[wcol + c];
            hi += bias[wcol + c + 1];
            *reinterpret_cast<float2*>(outp + c) = make_float2(lo, hi);
        }
    }
}

// ---------------- scatter: one warp per (edge, path) ------------------------
__device__ __forceinline__ void red_add_v4(float* addr, float4 v) {
    asm volatile("red.global.add.v4.f32 [%0], {%1, %2, %3, %4};"
                 :: "l"(addr), "f"(v.x), "f"(v.y), "f"(v.z), "f"(v.w)
                 : "memory");
}

__global__ __launch_bounds__(256) void scatter_kernel(
    const int* __restrict__ ei0, const int* __restrict__ ei1)
{
    int w = (blockIdx.x * 256 + threadIdx.x) >> 5;
    int lane = threadIdx.x & 31;
    if (w >= 2 * NE) return;
    int p = (w >= NE) ? 1 : 0;
    int e = w - p * NE;
    const int* __restrict__ ei = p ? ei1 : ei0;
    int src = ei[e];            // row 0 of (2,E)
    int dst = ei[e + NE];       // row 1 of (2,E)

    const float4* prow = reinterpret_cast<const float4*>(
        g_proj + (size_t)src * 512 + p * 256);
    float4 v0 = prow[lane * 2];
    float4 v1 = prow[lane * 2 + 1];

    float* arow = g_agg + ((size_t)p * NA + dst) * 256;
    red_add_v4(arow + lane * 8,     v0);
    red_add_v4(arow + lane * 8 + 4, v1);
    if (lane == 0) atomicAdd(&g_cnt[p * NA + dst], 1.0f);
}

// ---------------- finalize: one warp per destination row --------------------
__global__ __launch_bounds__(256) void finalize_kernel(
    const float* __restrict__ sem, const float* __restrict__ gamma,
    const float* __restrict__ beta, float* __restrict__ outA)
{
    int n = (blockIdx.x * 256 + threadIdx.x) >> 5;
    int lane = threadIdx.x & 31;
    if (n >= NA) return;
    int base = lane * 8;

    const float* a0p = g_agg + (size_t)n * 256;
    const float* a1p = g_agg + ((size_t)NA + n) * 256;

    float a0[8], a1[8], sv[8];
    *reinterpret_cast<float4*>(&a0[0]) = *reinterpret_cast<const float4*>(a0p + base);
    *reinterpret_cast<float4*>(&a0[4]) = *reinterpret_cast<const float4*>(a0p + base + 4);
    *reinterpret_cast<float4*>(&a1[0]) = *reinterpret_cast<const float4*>(a1p + base);
    *reinterpret_cast<float4*>(&a1[4]) = *reinterpret_cast<const float4*>(a1p + base + 4);
    *reinterpret_cast<float4*>(&sv[0]) = *reinterpret_cast<const float4*>(sem + base);
    *reinterpret_cast<float4*>(&sv[4]) = *reinterpret_cast<const float4*>(sem + base + 4);

    float inv0 = 1.0f / fmaxf(g_cnt[n], 1.0f);
    float inv1 = 1.0f / fmaxf(g_cnt[NA + n], 1.0f);

    float s0 = 0.f, s1 = 0.f;
#pragma unroll
    for (int i = 0; i < 8; i++) {
        a0[i] *= inv0;
        a1[i] *= inv1;
        s0 += tanhf(a0[i]) * sv[i];
        s1 += tanhf(a1[i]) * sv[i];
    }
#pragma unroll
    for (int o = 16; o > 0; o >>= 1) {
        s0 += __shfl_xor_sync(0xffffffffu, s0, o);
        s1 += __shfl_xor_sync(0xffffffffu, s1, o);
    }
    float m = fmaxf(s0, s1);
    float e0 = __expf(s0 - m), e1 = __expf(s1 - m);
    float w0 = e0 / (e0 + e1);
    float w1 = 1.0f - w0;

    float f[8];
    float sum = 0.f, sq = 0.f;
#pragma unroll
    for (int i = 0; i < 8; i++) {
        f[i] = fmaxf(w0 * a0[i] + w1 * a1[i], 0.f);
        sum += f[i];
        sq  += f[i] * f[i];
    }
#pragma unroll
    for (int o = 16; o > 0; o >>= 1) {
        sum += __shfl_xor_sync(0xffffffffu, sum, o);
        sq  += __shfl_xor_sync(0xffffffffu, sq, o);
    }
    float mu  = sum * (1.0f / 256.0f);
    float var = sq * (1.0f / 256.0f) - mu * mu;
    float rstd = rsqrtf(var + LN_EPS);

    float gm[8], bt[8];
    *reinterpret_cast<float4*>(&gm[0]) = *reinterpret_cast<const float4*>(gamma + base);
    *reinterpret_cast<float4*>(&gm[4]) = *reinterpret_cast<const float4*>(gamma + base + 4);
    *reinterpret_cast<float4*>(&bt[0]) = *reinterpret_cast<const float4*>(beta + base);
    *reinterpret_cast<float4*>(&bt[4]) = *reinterpret_cast<const float4*>(beta + base + 4);

    float o8[8];
#pragma unroll
    for (int i = 0; i < 8; i++)
        o8[i] = (f[i] - mu) * rstd * gm[i] + bt[i];

    float* op = outA + (size_t)n * 256 + base;
    *reinterpret_cast<float4*>(op)     = *reinterpret_cast<float4*>(&o8[0]);
    *reinterpret_cast<float4*>(op + 4) = *reinterpret_cast<float4*>(&o8[4]);
}

// ---------------- launch ----------------------------------------------------
extern "C" void kernel_launch(void* const* d_in, const int* in_sizes, int n_in,
                              void* d_out, int out_size)
{
    // metadata order: x_A, x_B, edge_index0, edge_index1, W0, b0, W1, b1,
    //                 sem_vec, gamma, beta
    const float* x_B  = (const float*)d_in[1];
    const int*   ei0  = (const int*)d_in[2];
    const int*   ei1  = (const int*)d_in[3];
    const float* W0   = (const float*)d_in[4];
    const float* b0   = (const float*)d_in[5];
    const float* W1   = (const float*)d_in[6];
    const float* b1   = (const float*)d_in[7];
    const float* sem  = (const float*)d_in[8];
    const float* gam  = (const float*)d_in[9];
    const float* bet  = (const float*)d_in[10];

    float* outA = (float*)d_out;
    float* outB = outA + (size_t)NA * OUT_DIM;

    // 1) zero aggregation scratch + counts
    {
        size_t total = (size_t)2 * NA * 256 / 4 + (size_t)2 * NA / 4;
        int blocks = (int)((total + 255) / 256);
        zero_scratch_kernel<<<blocks, 256>>>();
    }
    // 2) zero out_B half of the output
    {
        size_t total = (size_t)NB * OUT_DIM / 4;
        int blocks = (int)((total + 255) / 256);
        zero_outB_kernel<<<blocks, 256>>>(outB);
    }
    // 3) dual projection GEMM
    {
        dim3 grid((NB + 127) / 128, 4);
        gemm_dual_kernel<<<grid, 256>>>(x_B, W0, b0, W1, b1);
    }
    // 4) edge scatter (mean numerator + counts)
    {
        int warps = 2 * NE;
        int blocks = (warps * 32 + 255) / 256;
        scatter_kernel<<<blocks, 256>>>(ei0, ei1);
    }
    // 5) semantic attention + relu + layernorm
    {
        int blocks = (NA * 32 + 255) / 256;
        finalize_kernel<<<blocks, 256>>>(sem, gam, bet, outA);
    }
}

// round 3
// speedup vs baseline: 1.2098x; 1.2098x over previous
#include <cuda_runtime.h>
#include <cuda_bf16.h>
#include <cstdint>

#define NA 100000
#define NB 100000
#define IN_DIM 256
#define OUT_DIM 256
#define NE 320000
#define LN_EPS 1e-5f

// ---------------- scratch (device globals; no allocation allowed) -----------
__device__ float g_S[(size_t)2 * NA * 256];          // scatter sums [2][NA][256]
__device__ float g_agg[(size_t)2 * NA * 256];        // per-path mean+bias [2][NA][256]
__device__ float g_cnt[2 * NA];                      // [2][NA]
__device__ __nv_bfloat16 g_Wt_hi[512 * 256];         // Wcat^T [n][k], bf16 hi
__device__ __nv_bfloat16 g_Wt_lo[512 * 256];         // bf16 lo (residual)

// ---------------- helpers ----------------------------------------------------
__device__ __forceinline__ uint32_t smem_u32(const void* p) {
    uint32_t a;
    asm("{ .reg .u64 t; cvta.to.shared.u64 t, %1; cvt.u32.u64 %0, t; }" : "=r"(a) : "l"(p));
    return a;
}
__device__ __forceinline__ void ldsm_x4(uint32_t& r0, uint32_t& r1, uint32_t& r2,
                                        uint32_t& r3, uint32_t addr) {
    asm volatile("ldmatrix.sync.aligned.m8n8.x4.shared.b16 {%0,%1,%2,%3}, [%4];"
                 : "=r"(r0), "=r"(r1), "=r"(r2), "=r"(r3) : "r"(addr));
}
__device__ __forceinline__ void mma_bf16(float* c, const uint32_t* a, const uint32_t* b) {
    asm volatile("mma.sync.aligned.m16n8k16.row.col.f32.bf16.bf16.f32 "
                 "{%0,%1,%2,%3}, {%4,%5,%6,%7}, {%8,%9}, {%0,%1,%2,%3};"
                 : "+f"(c[0]), "+f"(c[1]), "+f"(c[2]), "+f"(c[3])
                 : "r"(a[0]), "r"(a[1]), "r"(a[2]), "r"(a[3]), "r"(b[0]), "r"(b[1]));
}
__device__ __forceinline__ void red_add_v4(float* addr, float4 v) {
    asm volatile("red.global.add.v4.f32 [%0], {%1, %2, %3, %4};"
                 :: "l"(addr), "f"(v.x), "f"(v.y), "f"(v.z), "f"(v.w)
                 : "memory");
}

// ---------------- combined zero kernel --------------------------------------
__global__ __launch_bounds__(256) void zero_all_kernel(float* __restrict__ outB) {
    size_t i = (size_t)blockIdx.x * 256 + threadIdx.x;
    const size_t n4_S = (size_t)2 * NA * 256 / 4;     // 12,800,000
    const size_t n4_cnt = (size_t)2 * NA / 4;         // 50,000
    const size_t n4_outB = (size_t)NB * OUT_DIM / 4;  // 6,400,000
    float4 z = make_float4(0.f, 0.f, 0.f, 0.f);
    if (i < n4_S) {
        reinterpret_cast<float4*>(g_S)[i] = z;
    } else if (i < n4_S + n4_cnt) {
        reinterpret_cast<float4*>(g_cnt)[i - n4_S] = z;
    } else if (i < n4_S + n4_cnt + n4_outB) {
        reinterpret_cast<float4*>(outB)[i - n4_S - n4_cnt] = z;
    }
}

// ---------------- W split/transpose prep ------------------------------------
__global__ __launch_bounds__(256) void splitW_kernel(const float* __restrict__ W0,
                                                     const float* __restrict__ W1) {
    int n = blockIdx.x;          // 0..511 (Wcat column)
    int k = threadIdx.x;         // 0..255
    float w = (n < 256) ? W0[k * 256 + n] : W1[k * 256 + (n - 256)];
    __nv_bfloat16 h = __float2bfloat16_rn(w);
    float r = w - __bfloat162float(h);
    g_Wt_hi[n * 256 + k] = h;
    g_Wt_lo[n * 256 + k] = __float2bfloat16_rn(r);
}

// ---------------- scatter: one warp per (edge, path), raw x_B rows ----------
__global__ __launch_bounds__(256) void scatter_kernel(
    const float* __restrict__ xB,
    const int* __restrict__ ei0, const int* __restrict__ ei1)
{
    int w = (blockIdx.x * 256 + threadIdx.x) >> 5;
    int lane = threadIdx.x & 31;
    if (w >= 2 * NE) return;
    int p = (w >= NE) ? 1 : 0;
    int e = w - p * NE;
    const int* __restrict__ ei = p ? ei1 : ei0;
    int src = ei[e];            // row 0 of (2,E)
    int dst = ei[e + NE];       // row 1 of (2,E)

    const float4* prow = reinterpret_cast<const float4*>(xB + (size_t)src * 256);
    float4 v0 = prow[lane * 2];
    float4 v1 = prow[lane * 2 + 1];

    float* arow = g_S + ((size_t)p * NA + dst) * 256;
    red_add_v4(arow + lane * 8,     v0);
    red_add_v4(arow + lane * 8 + 4, v1);
    if (lane == 0) atomicAdd(&g_cnt[p * NA + dst], 1.0f);
}

// ---------------- HMMA GEMM: agg = (S @ W)/cnt + b -------------------------
// grid (ceil(NA/128), 4): y = p*2 + h; CTA computes agg[p][m0:+128][h*128:+128].
// bf16 3-pass split, fp32 accum. 256 threads = 8 warps, warp tile 32x64.
#define SMA_HI 0
#define SMA_LO 16384
#define SMB_HI 32768
#define SMB_LO 49152
#define GSM_TOTAL 65536

__global__ __launch_bounds__(256) void gemm_mma_kernel(
    const float* __restrict__ b0, const float* __restrict__ b1)
{
    extern __shared__ char smem[];
    const uint32_t sbase = smem_u32(smem);
    const int tid = threadIdx.x, lane = tid & 31, wid = tid >> 5;
    const int wm = wid & 3;          // m offset = wm*32
    const int wn = wid >> 2;         // n offset = wn*64
    const int m0 = blockIdx.x * 128;
    const int p = blockIdx.y >> 1, h = blockIdx.y & 1;

    const float* __restrict__ Ssrc = g_S + (size_t)p * NA * 256;

    float c[2][8][4];
#pragma unroll
    for (int mt = 0; mt < 2; mt++)
#pragma unroll
        for (int n8 = 0; n8 < 8; n8++)
#pragma unroll
            for (int q = 0; q < 4; q++) c[mt][n8][q] = 0.f;

    // per-thread ldmatrix row/offset components
    const int am = lane & 15;              // A matrix row within 16
    const int aoff = lane >> 4;            // A kunit offset (0/1)
    const int asw = am & 7;
    const int bn = (lane & 7) | ((lane & 16) >> 1);  // B row (n) within 16
    const int boff = (lane >> 3) & 1;      // B kunit offset (0/1)
    const int bsw = bn & 7;

    for (int kc = 0; kc < 4; kc++) {
        // ---- load A chunk: S rows, fp32 -> bf16 hi/lo, swizzled ------------
#pragma unroll
        for (int l = 0; l < 4; l++) {
            int u = l * 256 + tid;
            int r = u >> 3, cu = u & 7;
            int grow = m0 + r;
            float4 v0 = make_float4(0.f, 0.f, 0.f, 0.f), v1 = v0;
            if (grow < NA) {
                const float* sp = Ssrc + (size_t)grow * 256 + kc * 64 + cu * 8;
                v0 = *reinterpret_cast<const float4*>(sp);
                v1 = *reinterpret_cast<const float4*>(sp + 4);
            }
            __nv_bfloat162 h0 = __floats2bfloat162_rn(v0.x, v0.y);
            __nv_bfloat162 h1 = __floats2bfloat162_rn(v0.z, v0.w);
            __nv_bfloat162 h2 = __floats2bfloat162_rn(v1.x, v1.y);
            __nv_bfloat162 h3 = __floats2bfloat162_rn(v1.z, v1.w);
            __nv_bfloat162 l0 = __floats2bfloat162_rn(v0.x - __bfloat162float(h0.x),
                                                      v0.y - __bfloat162float(h0.y));
            __nv_bfloat162 l1 = __floats2bfloat162_rn(v0.z - __bfloat162float(h1.x),
                                                      v0.w - __bfloat162float(h1.y));
            __nv_bfloat162 l2 = __floats2bfloat162_rn(v1.x - __bfloat162float(h2.x),
                                                      v1.y - __bfloat162float(h2.y));
            __nv_bfloat162 l3 = __floats2bfloat162_rn(v1.z - __bfloat162float(h3.x),
                                                      v1.w - __bfloat162float(h3.y));
            uint32_t off = (uint32_t)(r * 128 + (cu ^ (r & 7)) * 16);
            uint4 hv, lv;
            hv.x = *reinterpret_cast<uint32_t*>(&h0); hv.y = *reinterpret_cast<uint32_t*>(&h1);
            hv.z = *reinterpret_cast<uint32_t*>(&h2); hv.w = *reinterpret_cast<uint32_t*>(&h3);
            lv.x = *reinterpret_cast<uint32_t*>(&l0); lv.y = *reinterpret_cast<uint32_t*>(&l1);
            lv.z = *reinterpret_cast<uint32_t*>(&l2); lv.w = *reinterpret_cast<uint32_t*>(&l3);
            *reinterpret_cast<uint4*>(smem + SMA_HI + off) = hv;
            *reinterpret_cast<uint4*>(smem + SMA_LO + off) = lv;
        }
        // ---- load B chunk: precomputed bf16 hi/lo, swizzled ---------------
#pragma unroll
        for (int l = 0; l < 4; l++) {
            int u = l * 256 + tid;
            int n = u >> 3, cu = u & 7;
            size_t gsrc = (size_t)(p * 256 + h * 128 + n) * 256 + kc * 64 + cu * 8;
            uint32_t off = (uint32_t)(n * 128 + (cu ^ (n & 7)) * 16);
            *reinterpret_cast<uint4*>(smem + SMB_HI + off) =
                *reinterpret_cast<const uint4*>(g_Wt_hi + gsrc);
            *reinterpret_cast<uint4*>(smem + SMB_LO + off) =
                *reinterpret_cast<const uint4*>(g_Wt_lo + gsrc);
        }
        __syncthreads();

        // ---- 4 k16 steps ---------------------------------------------------
#pragma unroll
        for (int s = 0; s < 4; s++) {
            uint32_t ah[2][4], al[2][4], bh[4][4], bl[4][4];
#pragma unroll
            for (int mt = 0; mt < 2; mt++) {
                int arow = wm * 32 + mt * 16 + am;
                uint32_t abyte = (uint32_t)(arow * 128 + (((s << 1) | aoff) ^ asw) * 16);
                ldsm_x4(ah[mt][0], ah[mt][1], ah[mt][2], ah[mt][3], sbase + SMA_HI + abyte);
                ldsm_x4(al[mt][0], al[mt][1], al[mt][2], al[mt][3], sbase + SMA_LO + abyte);
            }
#pragma unroll
            for (int g = 0; g < 4; g++) {
                int brow = wn * 64 + g * 16 + bn;
                uint32_t bbyte = (uint32_t)(brow * 128 + (((s << 1) | boff) ^ bsw) * 16);
                ldsm_x4(bh[g][0], bh[g][1], bh[g][2], bh[g][3], sbase + SMB_HI + bbyte);
                ldsm_x4(bl[g][0], bl[g][1], bl[g][2], bl[g][3], sbase + SMB_LO + bbyte);
            }
#pragma unroll
            for (int mt = 0; mt < 2; mt++)
#pragma unroll
                for (int g = 0; g < 4; g++) {
                    mma_bf16(c[mt][2 * g],     ah[mt], &bh[g][0]);
                    mma_bf16(c[mt][2 * g],     ah[mt], &bl[g][0]);
                    mma_bf16(c[mt][2 * g],     al[mt], &bh[g][0]);
                    mma_bf16(c[mt][2 * g + 1], ah[mt], &bh[g][2]);
                    mma_bf16(c[mt][2 * g + 1], ah[mt], &bl[g][2]);
                    mma_bf16(c[mt][2 * g + 1], al[mt], &bh[g][2]);
                }
        }
        __syncthreads();
    }

    // ---- epilogue: mean + bias -> g_agg ------------------------------------
    const float* __restrict__ bias = p ? b1 : b0;
    float* __restrict__ dst = g_agg + (size_t)p * NA * 256;
#pragma unroll
    for (int mt = 0; mt < 2; mt++) {
#pragma unroll
        for (int rr = 0; rr < 2; rr++) {
            int row = m0 + wm * 32 + mt * 16 + rr * 8 + (lane >> 2);
            if (row >= NA) continue;
            float cv = g_cnt[p * NA + row];
            float inv = cv > 0.f ? 1.f / cv : 0.f;
            float bf = cv > 0.f ? 1.f : 0.f;
            float* orow = dst + (size_t)row * 256;
#pragma unroll
            for (int n8 = 0; n8 < 8; n8++) {
                int col = h * 128 + wn * 64 + n8 * 8 + (lane & 3) * 2;
                float2 o;
                o.x = c[mt][n8][rr * 2 + 0] * inv + bias[col] * bf;
                o.y = c[mt][n8][rr * 2 + 1] * inv + bias[col + 1] * bf;
                *reinterpret_cast<float2*>(orow + col) = o;
            }
        }
    }
}

// ---------------- finalize: one warp per destination row --------------------
__global__ __launch_bounds__(256) void finalize_kernel(
    const float* __restrict__ sem, const float* __restrict__ gamma,
    const float* __restrict__ beta, float* __restrict__ outA)
{
    int n = (blockIdx.x * 256 + threadIdx.x) >> 5;
    int lane = threadIdx.x & 31;
    if (n >= NA) return;
    int base = lane * 8;

    const float* a0p = g_agg + (size_t)n * 256;
    const float* a1p = g_agg + ((size_t)NA + n) * 256;

    float a0[8], a1[8], sv[8];
    *reinterpret_cast<float4*>(&a0[0]) = *reinterpret_cast<const float4*>(a0p + base);
    *reinterpret_cast<float4*>(&a0[4]) = *reinterpret_cast<const float4*>(a0p + base + 4);
    *reinterpret_cast<float4*>(&a1[0]) = *reinterpret_cast<const float4*>(a1p + base);
    *reinterpret_cast<float4*>(&a1[4]) = *reinterpret_cast<const float4*>(a1p + base + 4);
    *reinterpret_cast<float4*>(&sv[0]) = *reinterpret_cast<const float4*>(sem + base);
    *reinterpret_cast<float4*>(&sv[4]) = *reinterpret_cast<const float4*>(sem + base + 4);

    float s0 = 0.f, s1 = 0.f;
#pragma unroll
    for (int i = 0; i < 8; i++) {
        s0 += tanhf(a0[i]) * sv[i];
        s1 += tanhf(a1[i]) * sv[i];
    }
#pragma unroll
    for (int o = 16; o > 0; o >>= 1) {
        s0 += __shfl_xor_sync(0xffffffffu, s0, o);
        s1 += __shfl_xor_sync(0xffffffffu, s1, o);
    }
    float m = fmaxf(s0, s1);
    float e0 = __expf(s0 - m), e1 = __expf(s1 - m);
    float w0 = e0 / (e0 + e1);
    float w1 = 1.0f - w0;

    float f[8];
    float sum = 0.f, sq = 0.f;
#pragma unroll
    for (int i = 0; i < 8; i++) {
        f[i] = fmaxf(w0 * a0[i] + w1 * a1[i], 0.f);
        sum += f[i];
        sq  += f[i] * f[i];
    }
#pragma unroll
    for (int o = 16; o > 0; o >>= 1) {
        sum += __shfl_xor_sync(0xffffffffu, sum, o);
        sq  += __shfl_xor_sync(0xffffffffu, sq, o);
    }
    float mu  = sum * (1.0f / 256.0f);
    float var = sq * (1.0f / 256.0f) - mu * mu;
    float rstd = rsqrtf(var + LN_EPS);

    float gm[8], bt[8];
    *reinterpret_cast<float4*>(&gm[0]) = *reinterpret_cast<const float4*>(gamma + base);
    *reinterpret_cast<float4*>(&gm[4]) = *reinterpret_cast<const float4*>(gamma + base + 4);
    *reinterpret_cast<float4*>(&bt[0]) = *reinterpret_cast<const float4*>(beta + base);
    *reinterpret_cast<float4*>(&bt[4]) = *reinterpret_cast<const float4*>(beta + base + 4);

    float o8[8];
#pragma unroll
    for (int i = 0; i < 8; i++)
        o8[i] = (f[i] - mu) * rstd * gm[i] + bt[i];

    float* op = outA + (size_t)n * 256 + base;
    *reinterpret_cast<float4*>(op)     = *reinterpret_cast<float4*>(&o8[0]);
    *reinterpret_cast<float4*>(op + 4) = *reinterpret_cast<float4*>(&o8[4]);
}

// ---------------- launch ----------------------------------------------------
extern "C" void kernel_launch(void* const* d_in, const int* in_sizes, int n_in,
                              void* d_out, int out_size)
{
    const float* x_B  = (const float*)d_in[1];
    const int*   ei0  = (const int*)d_in[2];
    const int*   ei1  = (const int*)d_in[3];
    const float* W0   = (const float*)d_in[4];
    const float* b0   = (const float*)d_in[5];
    const float* W1   = (const float*)d_in[6];
    const float* b1   = (const float*)d_in[7];
    const float* sem  = (const float*)d_in[8];
    const float* gam  = (const float*)d_in[9];
    const float* bet  = (const float*)d_in[10];

    float* outA = (float*)d_out;
    float* outB = outA + (size_t)NA * OUT_DIM;

    cudaFuncSetAttribute(gemm_mma_kernel,
                         cudaFuncAttributeMaxDynamicSharedMemorySize, GSM_TOTAL);

    // 1) zero S + cnt + out_B
    {
        size_t total = (size_t)2 * NA * 256 / 4 + (size_t)2 * NA / 4
                     + (size_t)NB * OUT_DIM / 4;
        int blocks = (int)((total + 255) / 256);
        zero_all_kernel<<<blocks, 256>>>(outB);
    }
    // 2) split + transpose W -> bf16 hi/lo
    splitW_kernel<<<512, 256>>>(W0, W1);
    // 3) edge scatter of raw x_B rows (sums + counts)
    {
        int warps = 2 * NE;
        int blocks = (warps * 32 + 255) / 256;
        scatter_kernel<<<blocks, 256>>>(x_B, ei0, ei1);
    }
    // 4) HMMA GEMM: agg = (S @ W)/cnt + b
    {
        dim3 grid((NA + 127) / 128, 4);
        gemm_mma_kernel<<<grid, 256, GSM_TOTAL>>>(b0, b1);
    }
    // 5) semantic attention + relu + layernorm
    {
        int blocks = (NA * 32 + 255) / 256;
        finalize_kernel<<<blocks, 256>>>(sem, gam, bet, outA);
    }
}

// round 4
// speedup vs baseline: 1.4919x; 1.2332x over previous
#include <cuda_runtime.h>
#include <cuda_bf16.h>
#include <cstdint>

#define NA 100000
#define NB 100000
#define IN_DIM 256
#define OUT_DIM 256
#define NE 320000
#define LN_EPS 1e-5f

// ---------------- scratch (device globals; no allocation allowed) -----------
__device__ float g_S[(size_t)2 * NA * 256];          // scatter sums [2][NA][256]
__device__ float g_agg[(size_t)2 * NA * 256];        // per-path mean+bias [2][NA][256]
__device__ float g_cnt[2 * NA];                      // [2][NA]
__device__ __nv_bfloat16 g_Wt_hi[512 * 256];         // Wcat^T [n][k], bf16 hi
__device__ __nv_bfloat16 g_Wt_lo[512 * 256];         // bf16 lo (residual)

// ---------------- helpers ----------------------------------------------------
__device__ __forceinline__ uint32_t smem_u32(const void* p) {
    uint32_t a;
    asm("{ .reg .u64 t; cvta.to.shared.u64 t, %1; cvt.u32.u64 %0, t; }" : "=r"(a) : "l"(p));
    return a;
}
__device__ __forceinline__ void ldsm_x4(uint32_t& r0, uint32_t& r1, uint32_t& r2,
                                        uint32_t& r3, uint32_t addr) {
    asm volatile("ldmatrix.sync.aligned.m8n8.x4.shared.b16 {%0,%1,%2,%3}, [%4];"
                 : "=r"(r0), "=r"(r1), "=r"(r2), "=r"(r3) : "r"(addr));
}
__device__ __forceinline__ void mma_bf16(float* c, const uint32_t* a, const uint32_t* b) {
    asm volatile("mma.sync.aligned.m16n8k16.row.col.f32.bf16.bf16.f32 "
                 "{%0,%1,%2,%3}, {%4,%5,%6,%7}, {%8,%9}, {%0,%1,%2,%3};"
                 : "+f"(c[0]), "+f"(c[1]), "+f"(c[2]), "+f"(c[3])
                 : "r"(a[0]), "r"(a[1]), "r"(a[2]), "r"(a[3]), "r"(b[0]), "r"(b[1]));
}
__device__ __forceinline__ void red_add_v4(float* addr, float4 v) {
    asm volatile("red.global.add.v4.f32 [%0], {%1, %2, %3, %4};"
                 :: "l"(addr), "f"(v.x), "f"(v.y), "f"(v.z), "f"(v.w)
                 : "memory");
}
#define CP_ASYNC16(sm, gp) \
    asm volatile("cp.async.cg.shared.global [%0], [%1], 16;" \
                 :: "r"(sm), "l"(gp) : "memory")
#define CP_COMMIT() asm volatile("cp.async.commit_group;" ::: "memory")
#define CP_WAIT0()  asm volatile("cp.async.wait_group 0;" ::: "memory")

// ---------------- combined zero kernel --------------------------------------
__global__ __launch_bounds__(256) void zero_all_kernel(float* __restrict__ outB) {
    size_t i = (size_t)blockIdx.x * 256 + threadIdx.x;
    const size_t n4_S = (size_t)2 * NA * 256 / 4;
    const size_t n4_cnt = (size_t)2 * NA / 4;
    const size_t n4_outB = (size_t)NB * OUT_DIM / 4;
    float4 z = make_float4(0.f, 0.f, 0.f, 0.f);
    if (i < n4_S) {
        reinterpret_cast<float4*>(g_S)[i] = z;
    } else if (i < n4_S + n4_cnt) {
        reinterpret_cast<float4*>(g_cnt)[i - n4_S] = z;
    } else if (i < n4_S + n4_cnt + n4_outB) {
        reinterpret_cast<float4*>(outB)[i - n4_S - n4_cnt] = z;
    }
}

// ---------------- W split/transpose prep ------------------------------------
__global__ __launch_bounds__(256) void splitW_kernel(const float* __restrict__ W0,
                                                     const float* __restrict__ W1) {
    int n = blockIdx.x;
    int k = threadIdx.x;
    float w = (n < 256) ? W0[k * 256 + n] : W1[k * 256 + (n - 256)];
    __nv_bfloat16 h = __float2bfloat16_rn(w);
    float r = w - __bfloat162float(h);
    g_Wt_hi[n * 256 + k] = h;
    g_Wt_lo[n * 256 + k] = __float2bfloat16_rn(r);
}

// ---------------- scatter: one warp per (edge, path), raw x_B rows ----------
__global__ __launch_bounds__(256) void scatter_kernel(
    const float* __restrict__ xB,
    const int* __restrict__ ei0, const int* __restrict__ ei1)
{
    int w = (blockIdx.x * 256 + threadIdx.x) >> 5;
    int lane = threadIdx.x & 31;
    if (w >= 2 * NE) return;
    int p = (w >= NE) ? 1 : 0;
    int e = w - p * NE;
    const int* __restrict__ ei = p ? ei1 : ei0;
    int src = ei[e];
    int dst = ei[e + NE];

    const float4* prow = reinterpret_cast<const float4*>(xB + (size_t)src * 256);
    float4 v0 = prow[lane * 2];
    float4 v1 = prow[lane * 2 + 1];

    float* arow = g_S + ((size_t)p * NA + dst) * 256;
    red_add_v4(arow + lane * 8,     v0);
    red_add_v4(arow + lane * 8 + 4, v1);
    if (lane == 0) atomicAdd(&g_cnt[p * NA + dst], 1.0f);
}

// ---------------- HMMA GEMM: agg = (S @ W)/cnt + b -------------------------
// grid (ceil(NA/128), 4): y = p*2 + h; CTA computes agg[p][m0:+128][h*128:+128].
// bf16 3-pass split, fp32 accum. 256 threads = 8 warps, warp tile 32x64.
// __launch_bounds__(256, 2): cap regs at 128 -> 2 CTAs/SM.
#define SMA_HI 0
#define SMA_LO 16384
#define SMB_HI 32768
#define SMB_LO 49152
#define GSM_TOTAL 65536

__global__ __launch_bounds__(256, 2) void gemm_mma_kernel(
    const float* __restrict__ b0, const float* __restrict__ b1)
{
    extern __shared__ char smem[];
    const uint32_t sbase = smem_u32(smem);
    const int tid = threadIdx.x, lane = tid & 31, wid = tid >> 5;
    const int wm = wid & 3;          // m offset = wm*32
    const int wn = wid >> 2;         // n offset = wn*64
    const int m0 = blockIdx.x * 128;
    const int p = blockIdx.y >> 1, h = blockIdx.y & 1;

    const float* __restrict__ Ssrc = g_S + (size_t)p * NA * 256;

    float c[2][8][4];
#pragma unroll
    for (int mt = 0; mt < 2; mt++)
#pragma unroll
        for (int n8 = 0; n8 < 8; n8++)
#pragma unroll
            for (int q = 0; q < 4; q++) c[mt][n8][q] = 0.f;

    const int am = lane & 15;
    const int aoff = lane >> 4;
    const int asw = am & 7;
    const int bn = (lane & 7) | ((lane & 16) >> 1);
    const int boff = (lane >> 3) & 1;
    const int bsw = bn & 7;

    for (int kc = 0; kc < 4; kc++) {
        // ---- B chunk via cp.async (bf16 hi/lo, swizzled dest) -------------
#pragma unroll
        for (int l = 0; l < 4; l++) {
            int u = l * 256 + tid;
            int n = u >> 3, cu = u & 7;
            size_t gsrc = (size_t)(p * 256 + h * 128 + n) * 256 + kc * 64 + cu * 8;
            uint32_t off = (uint32_t)(n * 128 + (cu ^ (n & 7)) * 16);
            CP_ASYNC16(sbase + SMB_HI + off, g_Wt_hi + gsrc);
            CP_ASYNC16(sbase + SMB_LO + off, g_Wt_lo + gsrc);
        }
        CP_COMMIT();

        // ---- A chunk: S rows, fp32 -> bf16 hi/lo, swizzled ----------------
#pragma unroll
        for (int l = 0; l < 4; l++) {
            int u = l * 256 + tid;
            int r = u >> 3, cu = u & 7;
            int grow = m0 + r;
            float4 v0 = make_float4(0.f, 0.f, 0.f, 0.f), v1 = v0;
            if (grow < NA) {
                const float* sp = Ssrc + (size_t)grow * 256 + kc * 64 + cu * 8;
                v0 = *reinterpret_cast<const float4*>(sp);
                v1 = *reinterpret_cast<const float4*>(sp + 4);
            }
            __nv_bfloat162 h0 = __floats2bfloat162_rn(v0.x, v0.y);
            __nv_bfloat162 h1 = __floats2bfloat162_rn(v0.z, v0.w);
            __nv_bfloat162 h2 = __floats2bfloat162_rn(v1.x, v1.y);
            __nv_bfloat162 h3 = __floats2bfloat162_rn(v1.z, v1.w);
            __nv_bfloat162 l0 = __floats2bfloat162_rn(v0.x - __bfloat162float(h0.x),
                                                      v0.y - __bfloat162float(h0.y));
            __nv_bfloat162 l1 = __floats2bfloat162_rn(v0.z - __bfloat162float(h1.x),
                                                      v0.w - __bfloat162float(h1.y));
            __nv_bfloat162 l2 = __floats2bfloat162_rn(v1.x - __bfloat162float(h2.x),
                                                      v1.y - __bfloat162float(h2.y));
            __nv_bfloat162 l3 = __floats2bfloat162_rn(v1.z - __bfloat162float(h3.x),
                                                      v1.w - __bfloat162float(h3.y));
            uint32_t off = (uint32_t)(r * 128 + (cu ^ (r & 7)) * 16);
            uint4 hv, lv;
            hv.x = *reinterpret_cast<uint32_t*>(&h0); hv.y = *reinterpret_cast<uint32_t*>(&h1);
            hv.z = *reinterpret_cast<uint32_t*>(&h2); hv.w = *reinterpret_cast<uint32_t*>(&h3);
            lv.x = *reinterpret_cast<uint32_t*>(&l0); lv.y = *reinterpret_cast<uint32_t*>(&l1);
            lv.z = *reinterpret_cast<uint32_t*>(&l2); lv.w = *reinterpret_cast<uint32_t*>(&l3);
            *reinterpret_cast<uint4*>(smem + SMA_HI + off) = hv;
            *reinterpret_cast<uint4*>(smem + SMA_LO + off) = lv;
        }
        CP_WAIT0();
        __syncthreads();

        // ---- 4 k16 steps ---------------------------------------------------
#pragma unroll
        for (int s = 0; s < 4; s++) {
            uint32_t ah[2][4], al[2][4];
#pragma unroll
            for (int mt = 0; mt < 2; mt++) {
                int arow = wm * 32 + mt * 16 + am;
                uint32_t abyte = (uint32_t)(arow * 128 + (((s << 1) | aoff) ^ asw) * 16);
                ldsm_x4(ah[mt][0], ah[mt][1], ah[mt][2], ah[mt][3], sbase + SMA_HI + abyte);
                ldsm_x4(al[mt][0], al[mt][1], al[mt][2], al[mt][3], sbase + SMA_LO + abyte);
            }
#pragma unroll
            for (int g = 0; g < 4; g++) {
                int brow = wn * 64 + g * 16 + bn;
                uint32_t bbyte = (uint32_t)(brow * 128 + (((s << 1) | boff) ^ bsw) * 16);
                uint32_t bh[4], bl[4];
                ldsm_x4(bh[0], bh[1], bh[2], bh[3], sbase + SMB_HI + bbyte);
                ldsm_x4(bl[0], bl[1], bl[2], bl[3], sbase + SMB_LO + bbyte);
#pragma unroll
                for (int mt = 0; mt < 2; mt++) {
                    mma_bf16(c[mt][2 * g],     ah[mt], &bh[0]);
                    mma_bf16(c[mt][2 * g],     ah[mt], &bl[0]);
                    mma_bf16(c[mt][2 * g],     al[mt], &bh[0]);
                    mma_bf16(c[mt][2 * g + 1], ah[mt], &bh[2]);
                    mma_bf16(c[mt][2 * g + 1], ah[mt], &bl[2]);
                    mma_bf16(c[mt][2 * g + 1], al[mt], &bh[2]);
                }
            }
        }
        __syncthreads();
    }

    // ---- epilogue: mean + bias -> g_agg ------------------------------------
    const float* __restrict__ bias = p ? b1 : b0;
    float* __restrict__ dst = g_agg + (size_t)p * NA * 256;
#pragma unroll
    for (int mt = 0; mt < 2; mt++) {
#pragma unroll
        for (int rr = 0; rr < 2; rr++) {
            int row = m0 + wm * 32 + mt * 16 + rr * 8 + (lane >> 2);
            if (row >= NA) continue;
            float cv = g_cnt[p * NA + row];
            float inv = cv > 0.f ? 1.f / cv : 0.f;
            float bf = cv > 0.f ? 1.f : 0.f;
            float* orow = dst + (size_t)row * 256;
#pragma unroll
            for (int n8 = 0; n8 < 8; n8++) {
                int col = h * 128 + wn * 64 + n8 * 8 + (lane & 3) * 2;
                float2 o;
                o.x = c[mt][n8][rr * 2 + 0] * inv + bias[col] * bf;
                o.y = c[mt][n8][rr * 2 + 1] * inv + bias[col + 1] * bf;
                *reinterpret_cast<float2*>(orow + col) = o;
            }
        }
    }
}

// ---------------- finalize: one warp per destination row --------------------
__global__ __launch_bounds__(256) void finalize_kernel(
    const float* __restrict__ sem, const float* __restrict__ gamma,
    const float* __restrict__ beta, float* __restrict__ outA)
{
    int n = (blockIdx.x * 256 + threadIdx.x) >> 5;
    int lane = threadIdx.x & 31;
    if (n >= NA) return;
    int base = lane * 8;

    const float* a0p = g_agg + (size_t)n * 256;
    const float* a1p = g_agg + ((size_t)NA + n) * 256;

    float a0[8], a1[8], sv[8];
    *reinterpret_cast<float4*>(&a0[0]) = *reinterpret_cast<const float4*>(a0p + base);
    *reinterpret_cast<float4*>(&a0[4]) = *reinterpret_cast<const float4*>(a0p + base + 4);
    *reinterpret_cast<float4*>(&a1[0]) = *reinterpret_cast<const float4*>(a1p + base);
    *reinterpret_cast<float4*>(&a1[4]) = *reinterpret_cast<const float4*>(a1p + base + 4);
    *reinterpret_cast<float4*>(&sv[0]) = *reinterpret_cast<const float4*>(sem + base);
    *reinterpret_cast<float4*>(&sv[4]) = *reinterpret_cast<const float4*>(sem + base + 4);

    float s0 = 0.f, s1 = 0.f;
#pragma unroll
    for (int i = 0; i < 8; i++) {
        s0 += tanhf(a0[i]) * sv[i];
        s1 += tanhf(a1[i]) * sv[i];
    }
#pragma unroll
    for (int o = 16; o > 0; o >>= 1) {
        s0 += __shfl_xor_sync(0xffffffffu, s0, o);
        s1 += __shfl_xor_sync(0xffffffffu, s1, o);
    }
    float m = fmaxf(s0, s1);
    float e0 = __expf(s0 - m), e1 = __expf(s1 - m);
    float w0 = e0 / (e0 + e1);
    float w1 = 1.0f - w0;

    float f[8];
    float sum = 0.f, sq = 0.f;
#pragma unroll
    for (int i = 0; i < 8; i++) {
        f[i] = fmaxf(w0 * a0[i] + w1 * a1[i], 0.f);
        sum += f[i];
        sq  += f[i] * f[i];
    }
#pragma unroll
    for (int o = 16; o > 0; o >>= 1) {
        sum += __shfl_xor_sync(0xffffffffu, sum, o);
        sq  += __shfl_xor_sync(0xffffffffu, sq, o);
    }
    float mu  = sum * (1.0f / 256.0f);
    float var = sq * (1.0f / 256.0f) - mu * mu;
    float rstd = rsqrtf(var + LN_EPS);

    float gm[8], bt[8];
    *reinterpret_cast<float4*>(&gm[0]) = *reinterpret_cast<const float4*>(gamma + base);
    *reinterpret_cast<float4*>(&gm[4]) = *reinterpret_cast<const float4*>(gamma + base + 4);
    *reinterpret_cast<float4*>(&bt[0]) = *reinterpret_cast<const float4*>(beta + base);
    *reinterpret_cast<float4*>(&bt[4]) = *reinterpret_cast<const float4*>(beta + base + 4);

    float o8[8];
#pragma unroll
    for (int i = 0; i < 8; i++)
        o8[i] = (f[i] - mu) * rstd * gm[i] + bt[i];

    float* op = outA + (size_t)n * 256 + base;
    *reinterpret_cast<float4*>(op)     = *reinterpret_cast<float4*>(&o8[0]);
    *reinterpret_cast<float4*>(op + 4) = *reinterpret_cast<float4*>(&o8[4]);
}

// ---------------- launch ----------------------------------------------------
extern "C" void kernel_launch(void* const* d_in, const int* in_sizes, int n_in,
                              void* d_out, int out_size)
{
    const float* x_B  = (const float*)d_in[1];
    const int*   ei0  = (const int*)d_in[2];
    const int*   ei1  = (const int*)d_in[3];
    const float* W0   = (const float*)d_in[4];
    const float* b0   = (const float*)d_in[5];
    const float* W1   = (const float*)d_in[6];
    const float* b1   = (const float*)d_in[7];
    const float* sem  = (const float*)d_in[8];
    const float* gam  = (const float*)d_in[9];
    const float* bet  = (const float*)d_in[10];

    float* outA = (float*)d_out;
    float* outB = outA + (size_t)NA * OUT_DIM;

    cudaFuncSetAttribute(gemm_mma_kernel,
                         cudaFuncAttributeMaxDynamicSharedMemorySize, GSM_TOTAL);

    // 1) zero S + cnt + out_B
    {
        size_t total = (size_t)2 * NA * 256 / 4 + (size_t)2 * NA / 4
                     + (size_t)NB * OUT_DIM / 4;
        int blocks = (int)((total + 255) / 256);
        zero_all_kernel<<<blocks, 256>>>(outB);
    }
    // 2) split + transpose W -> bf16 hi/lo
    splitW_kernel<<<512, 256>>>(W0, W1);
    // 3) edge scatter of raw x_B rows (sums + counts)
    {
        int warps = 2 * NE;
        int blocks = (warps * 32 + 255) / 256;
        scatter_kernel<<<blocks, 256>>>(x_B, ei0, ei1);
    }
    // 4) HMMA GEMM: agg = (S @ W)/cnt + b
    {
        dim3 grid((NA + 127) / 128, 4);
        gemm_mma_kernel<<<grid, 256, GSM_TOTAL>>>(b0, b1);
    }
    // 5) semantic attention + relu + layernorm
    {
        int blocks = (NA * 32 + 255) / 256;
        finalize_kernel<<<blocks, 256>>>(sem, gam, bet, outA);
    }
}

// round 5
// speedup vs baseline: 1.9351x; 1.2970x over previous
#include <cuda_runtime.h>
#include <cuda_bf16.h>
#include <cstdint>

#define NA 100000
#define NB 100000
#define IN_DIM 256
#define OUT_DIM 256
#define NE 320000
#define LN_EPS 1e-5f

#define NBIN (2 * NA)            // 200000 (p, dst) bins
#define SCAN_B 512
#define NBLK ((NBIN + SCAN_B - 1) / SCAN_B)   // 391

// ---------------- scratch (device globals; no allocation allowed) -----------
__device__ float g_agg[(size_t)2 * NA * 256];        // per-path mean+bias
__device__ float g_cnt[NBIN];
__device__ __nv_bfloat16 g_Shi[(size_t)NBIN * 256];  // aggregated sums, bf16 hi
__device__ __nv_bfloat16 g_Slo[(size_t)NBIN * 256];  // bf16 lo residual
__device__ __nv_bfloat16 g_Wt_hi[512 * 256];         // Wcat^T [n][k]
__device__ __nv_bfloat16 g_Wt_lo[512 * 256];
__device__ int g_hist[NBIN];
__device__ int g_rowptr[NBIN];
__device__ int g_cursor[NBIN];
__device__ int g_elist[2 * NE];
__device__ int g_blocksums[SCAN_B];
__device__ int g_blockoff[SCAN_B];

// ---------------- helpers ----------------------------------------------------
__device__ __forceinline__ uint32_t smem_u32(const void* p) {
    uint32_t a;
    asm("{ .reg .u64 t; cvta.to.shared.u64 t, %1; cvt.u32.u64 %0, t; }" : "=r"(a) : "l"(p));
    return a;
}
__device__ __forceinline__ void ldsm_x4(uint32_t& r0, uint32_t& r1, uint32_t& r2,
                                        uint32_t& r3, uint32_t addr) {
    asm volatile("ldmatrix.sync.aligned.m8n8.x4.shared.b16 {%0,%1,%2,%3}, [%4];"
                 : "=r"(r0), "=r"(r1), "=r"(r2), "=r"(r3) : "r"(addr));
}
__device__ __forceinline__ void mma_bf16(float* c, const uint32_t* a, const uint32_t* b) {
    asm volatile("mma.sync.aligned.m16n8k16.row.col.f32.bf16.bf16.f32 "
                 "{%0,%1,%2,%3}, {%4,%5,%6,%7}, {%8,%9}, {%0,%1,%2,%3};"
                 : "+f"(c[0]), "+f"(c[1]), "+f"(c[2]), "+f"(c[3])
                 : "r"(a[0]), "r"(a[1]), "r"(a[2]), "r"(a[3]), "r"(b[0]), "r"(b[1]));
}
#define CP_ASYNC16(sm, gp) \
    asm volatile("cp.async.cg.shared.global [%0], [%1], 16;" \
                 :: "r"(sm), "l"(gp) : "memory")
#define CP_ASYNC16Z(sm, gp, sz) \
    asm volatile("cp.async.cg.shared.global [%0], [%1], 16, %2;" \
                 :: "r"(sm), "l"(gp), "r"(sz) : "memory")
#define CP_COMMIT() asm volatile("cp.async.commit_group;" ::: "memory")
#define CP_WAIT0()  asm volatile("cp.async.wait_group 0;" ::: "memory")
#define CP_WAIT1()  asm volatile("cp.async.wait_group 1;" ::: "memory")

// ---------------- zero: out_B + hist -----------------------------------------
__global__ __launch_bounds__(256) void zero_kernel(float* __restrict__ outB) {
    size_t i = (size_t)blockIdx.x * 256 + threadIdx.x;
    const size_t n4_outB = (size_t)NB * OUT_DIM / 4;   // 6,400,000
    const size_t n4_hist = NBIN / 4;                   // 50,000
    if (i < n4_outB) {
        reinterpret_cast<float4*>(outB)[i] = make_float4(0.f, 0.f, 0.f, 0.f);
    } else if (i < n4_outB + n4_hist) {
        reinterpret_cast<int4*>(g_hist)[i - n4_outB] = make_int4(0, 0, 0, 0);
    }
}

// ---------------- W split/transpose prep ------------------------------------
__global__ __launch_bounds__(256) void splitW_kernel(const float* __restrict__ W0,
                                                     const float* __restrict__ W1) {
    int n = blockIdx.x;
    int k = threadIdx.x;
    float w = (n < 256) ? W0[k * 256 + n] : W1[k * 256 + (n - 256)];
    __nv_bfloat16 h = __float2bfloat16_rn(w);
    float r = w - __bfloat162float(h);
    g_Wt_hi[n * 256 + k] = h;
    g_Wt_lo[n * 256 + k] = __float2bfloat16_rn(r);
}

// ---------------- CSR build --------------------------------------------------
__global__ __launch_bounds__(256) void hist_kernel(
    const int* __restrict__ ei0, const int* __restrict__ ei1)
{
    int i = blockIdx.x * 256 + threadIdx.x;
    if (i >= 2 * NE) return;
    int p = (i >= NE) ? 1 : 0;
    int e = i - p * NE;
    const int* __restrict__ ei = p ? ei1 : ei0;
    int dst = ei[e + NE];
    atomicAdd(&g_hist[p * NA + dst], 1);
}

__global__ __launch_bounds__(SCAN_B) void scanA_kernel() {
    __shared__ int sh[SCAN_B];
    int i = blockIdx.x * SCAN_B + threadIdx.x;
    sh[threadIdx.x] = (i < NBIN) ? g_hist[i] : 0;
    __syncthreads();
    for (int d = SCAN_B / 2; d > 0; d >>= 1) {
        if (threadIdx.x < d) sh[threadIdx.x] += sh[threadIdx.x + d];
        __syncthreads();
    }
    if (threadIdx.x == 0) g_blocksums[blockIdx.x] = sh[0];
}

__global__ __launch_bounds__(SCAN_B) void scanB_kernel() {
    __shared__ int sh[SCAN_B];
    int tid = threadIdx.x;
    int v = (tid < NBLK) ? g_blocksums[tid] : 0;
    sh[tid] = v;
    __syncthreads();
    for (int d = 1; d < SCAN_B; d <<= 1) {
        int t = (tid >= d) ? sh[tid - d] : 0;
        __syncthreads();
        sh[tid] += t;
        __syncthreads();
    }
    if (tid < NBLK) g_blockoff[tid] = sh[tid] - v;   // exclusive
}

__global__ __launch_bounds__(SCAN_B) void scanC_kernel() {
    __shared__ int sh[SCAN_B];
    int tid = threadIdx.x;
    int i = blockIdx.x * SCAN_B + tid;
    int v = (i < NBIN) ? g_hist[i] : 0;
    sh[tid] = v;
    __syncthreads();
    for (int d = 1; d < SCAN_B; d <<= 1) {
        int t = (tid >= d) ? sh[tid - d] : 0;
        __syncthreads();
        sh[tid] += t;
        __syncthreads();
    }
    if (i < NBIN) {
        int excl = sh[tid] - v + g_blockoff[blockIdx.x];
        g_rowptr[i] = excl;
        g_cursor[i] = excl;
        g_cnt[i] = (float)v;
    }
}

__global__ __launch_bounds__(256) void fill_kernel(
    const int* __restrict__ ei0, const int* __restrict__ ei1)
{
    int i = blockIdx.x * 256 + threadIdx.x;
    if (i >= 2 * NE) return;
    int p = (i >= NE) ? 1 : 0;
    int e = i - p * NE;
    const int* __restrict__ ei = p ? ei1 : ei0;
    int src = ei[e];
    int dst = ei[e + NE];
    int pos = atomicAdd(&g_cursor[p * NA + dst], 1);
    g_elist[pos] = src;
}

// ---------------- aggregate: warp per (p, dst); output bf16 hi/lo ------------
__global__ __launch_bounds__(256) void agg_kernel(const float* __restrict__ xB) {
    int w = (blockIdx.x * 256 + threadIdx.x) >> 5;
    int lane = threadIdx.x & 31;
    if (w >= NBIN) return;
    int start = g_rowptr[w];
    int deg = g_hist[w];

    float a[8] = {0.f, 0.f, 0.f, 0.f, 0.f, 0.f, 0.f, 0.f};
    for (int j = 0; j < deg; j++) {
        int src = __ldg(&g_elist[start + j]);
        const float4* r4 = reinterpret_cast<const float4*>(xB + (size_t)src * 256) + lane * 2;
        float4 v0 = r4[0], v1 = r4[1];
        a[0] += v0.x; a[1] += v0.y; a[2] += v0.z; a[3] += v0.w;
        a[4] += v1.x; a[5] += v1.y; a[6] += v1.z; a[7] += v1.w;
    }

    uint4 hv, lv;
    {
        __nv_bfloat162 h0 = __floats2bfloat162_rn(a[0], a[1]);
        __nv_bfloat162 h1 = __floats2bfloat162_rn(a[2], a[3]);
        __nv_bfloat162 h2 = __floats2bfloat162_rn(a[4], a[5]);
        __nv_bfloat162 h3 = __floats2bfloat162_rn(a[6], a[7]);
        __nv_bfloat162 l0 = __floats2bfloat162_rn(a[0] - __bfloat162float(h0.x),
                                                  a[1] - __bfloat162float(h0.y));
        __nv_bfloat162 l1 = __floats2bfloat162_rn(a[2] - __bfloat162float(h1.x),
                                                  a[3] - __bfloat162float(h1.y));
        __nv_bfloat162 l2 = __floats2bfloat162_rn(a[4] - __bfloat162float(h2.x),
                                                  a[5] - __bfloat162float(h2.y));
        __nv_bfloat162 l3 = __floats2bfloat162_rn(a[6] - __bfloat162float(h3.x),
                                                  a[7] - __bfloat162float(h3.y));
        hv.x = *reinterpret_cast<uint32_t*>(&h0); hv.y = *reinterpret_cast<uint32_t*>(&h1);
        hv.z = *reinterpret_cast<uint32_t*>(&h2); hv.w = *reinterpret_cast<uint32_t*>(&h3);
        lv.x = *reinterpret_cast<uint32_t*>(&l0); lv.y = *reinterpret_cast<uint32_t*>(&l1);
        lv.z = *reinterpret_cast<uint32_t*>(&l2); lv.w = *reinterpret_cast<uint32_t*>(&l3);
    }
    *reinterpret_cast<uint4*>(g_Shi + (size_t)w * 256 + lane * 8) = hv;
    *reinterpret_cast<uint4*>(g_Slo + (size_t)w * 256 + lane * 8) = lv;
}

// ---------------- HMMA GEMM: agg = (S @ W)/cnt + b --------------------------
// grid (4, 782): bx = p*2+h (fast -> A-tile L2 reuse), by = m-tile.
// K-chunk 32, double-buffered cp.async. Smem row = [hi 64B | lo 64B], SW over
// 8 16B units. Per stage: A 16KB @0, B 16KB @16KB; 2 stages = 64KB.
#define GBUF 32768
#define GSM_TOTAL 65536

__device__ __forceinline__ void gemm_issue(
    uint32_t sb, int tid, int m0,
    const __nv_bfloat16* __restrict__ Ahi, const __nv_bfloat16* __restrict__ Alo,
    const __nv_bfloat16* __restrict__ Bhi, const __nv_bfloat16* __restrict__ Blo,
    int kc)
{
#pragma unroll
    for (int l = 0; l < 4; l++) {
        int ulin = l * 256 + tid;
        int r = ulin >> 3, u = ulin & 7;
        int grow = m0 + r;
        int ok = (grow < NA) ? 16 : 0;
        int grc = (grow < NA) ? grow : (NA - 1);
        uint32_t dst = sb + (uint32_t)(r * 128 + ((u ^ (r & 7)) << 4));
        const __nv_bfloat16* src = (u < 4)
            ? (Ahi + (size_t)grc * 256 + kc * 32 + (u & 3) * 8)
            : (Alo + (size_t)grc * 256 + kc * 32 + (u & 3) * 8);
        CP_ASYNC16Z(dst, src, ok);
    }
#pragma unroll
    for (int l = 0; l < 4; l++) {
        int ulin = l * 256 + tid;
        int n = ulin >> 3, u = ulin & 7;
        uint32_t dst = sb + 16384u + (uint32_t)(n * 128 + ((u ^ (n & 7)) << 4));
        const __nv_bfloat16* src = (u < 4)
            ? (Bhi + (size_t)n * 256 + kc * 32 + (u & 3) * 8)
            : (Blo + (size_t)n * 256 + kc * 32 + (u & 3) * 8);
        CP_ASYNC16(dst, src);
    }
    CP_COMMIT();
}

__global__ __launch_bounds__(256, 2) void gemm_mma_kernel(
    const float* __restrict__ b0, const float* __restrict__ b1)
{
    extern __shared__ char smem[];
    const uint32_t sbase = smem_u32(smem);
    const int tid = threadIdx.x, lane = tid & 31, wid = tid >> 5;
    const int wm = wid & 3;
    const int wn = wid >> 2;
    const int p = blockIdx.x >> 1, h = blockIdx.x & 1;
    const int m0 = blockIdx.y * 128;

    const __nv_bfloat16* __restrict__ Ahi = g_Shi + (size_t)p * NA * 256;
    const __nv_bfloat16* __restrict__ Alo = g_Slo + (size_t)p * NA * 256;
    const __nv_bfloat16* __restrict__ Bhi = g_Wt_hi + (size_t)(p * 256 + h * 128) * 256;
    const __nv_bfloat16* __restrict__ Blo = g_Wt_lo + (size_t)(p * 256 + h * 128) * 256;

    float c[2][8][4];
#pragma unroll
    for (int mt = 0; mt < 2; mt++)
#pragma unroll
        for (int n8 = 0; n8 < 8; n8++)
#pragma unroll
            for (int q = 0; q < 4; q++) c[mt][n8][q] = 0.f;

    const int am = lane & 15;
    const int aoff = lane >> 4;
    const int asw = am & 7;
    const int bn = (lane & 7) | ((lane & 16) >> 1);
    const int boff = (lane >> 3) & 1;
    const int bsw = bn & 7;

    gemm_issue(sbase, tid, m0, Ahi, Alo, Bhi, Blo, 0);

    for (int kc = 0; kc < 8; kc++) {
        if (kc < 7) {
            gemm_issue(sbase + ((kc + 1) & 1) * GBUF, tid, m0, Ahi, Alo, Bhi, Blo, kc + 1);
            CP_WAIT1();
        } else {
            CP_WAIT0();
        }
        __syncthreads();
        const uint32_t sb = sbase + (kc & 1) * GBUF;

#pragma unroll
        for (int s = 0; s < 2; s++) {
            const int uhi = (s << 1) | aoff;
            uint32_t ah[2][4], al[2][4];
#pragma unroll
            for (int mt = 0; mt < 2; mt++) {
                int arow = wm * 32 + mt * 16 + am;
                uint32_t rb = sb + (uint32_t)(arow * 128);
                ldsm_x4(ah[mt][0], ah[mt][1], ah[mt][2], ah[mt][3],
                        rb + ((uhi ^ asw) << 4));
                ldsm_x4(al[mt][0], al[mt][1], al[mt][2], al[mt][3],
                        rb + (((4 | uhi) ^ asw) << 4));
            }
            const int vhi = (s << 1) | boff;
#pragma unroll
            for (int g = 0; g < 4; g++) {
                int brow = wn * 64 + g * 16 + bn;
                uint32_t rb = sb + 16384u + (uint32_t)(brow * 128);
                uint32_t bh[4], bl[4];
                ldsm_x4(bh[0], bh[1], bh[2], bh[3], rb + ((vhi ^ bsw) << 4));
                ldsm_x4(bl[0], bl[1], bl[2], bl[3], rb + (((4 | vhi) ^ bsw) << 4));
#pragma unroll
                for (int mt = 0; mt < 2; mt++) {
                    mma_bf16(c[mt][2 * g],     ah[mt], &bh[0]);
                    mma_bf16(c[mt][2 * g],     ah[mt], &bl[0]);
                    mma_bf16(c[mt][2 * g],     al[mt], &bh[0]);
                    mma_bf16(c[mt][2 * g + 1], ah[mt], &bh[2]);
                    mma_bf16(c[mt][2 * g + 1], ah[mt], &bl[2]);
                    mma_bf16(c[mt][2 * g + 1], al[mt], &bh[2]);
                }
            }
        }
        __syncthreads();
    }

    // ---- epilogue: mean + bias -> g_agg ------------------------------------
    const float* __restrict__ bias = p ? b1 : b0;
    float* __restrict__ dst = g_agg + (size_t)p * NA * 256;
#pragma unroll
    for (int mt = 0; mt < 2; mt++) {
#pragma unroll
        for (int rr = 0; rr < 2; rr++) {
            int row = m0 + wm * 32 + mt * 16 + rr * 8 + (lane >> 2);
            if (row >= NA) continue;
            float cv = g_cnt[p * NA + row];
            float inv = cv > 0.f ? 1.f / cv : 0.f;
            float bf = cv > 0.f ? 1.f : 0.f;
            float* orow = dst + (size_t)row * 256;
#pragma unroll
            for (int n8 = 0; n8 < 8; n8++) {
                int col = h * 128 + wn * 64 + n8 * 8 + (lane & 3) * 2;
                float2 o;
                o.x = c[mt][n8][rr * 2 + 0] * inv + bias[col] * bf;
                o.y = c[mt][n8][rr * 2 + 1] * inv + bias[col + 1] * bf;
                *reinterpret_cast<float2*>(orow + col) = o;
            }
        }
    }
}

// ---------------- finalize: one warp per destination row --------------------
__global__ __launch_bounds__(256) void finalize_kernel(
    const float* __restrict__ sem, const float* __restrict__ gamma,
    const float* __restrict__ beta, float* __restrict__ outA)
{
    int n = (blockIdx.x * 256 + threadIdx.x) >> 5;
    int lane = threadIdx.x & 31;
    if (n >= NA) return;
    int base = lane * 8;

    const float* a0p = g_agg + (size_t)n * 256;
    const float* a1p = g_agg + ((size_t)NA + n) * 256;

    float a0[8], a1[8], sv[8];
    *reinterpret_cast<float4*>(&a0[0]) = *reinterpret_cast<const float4*>(a0p + base);
    *reinterpret_cast<float4*>(&a0[4]) = *reinterpret_cast<const float4*>(a0p + base + 4);
    *reinterpret_cast<float4*>(&a1[0]) = *reinterpret_cast<const float4*>(a1p + base);
    *reinterpret_cast<float4*>(&a1[4]) = *reinterpret_cast<const float4*>(a1p + base + 4);
    *reinterpret_cast<float4*>(&sv[0]) = *reinterpret_cast<const float4*>(sem + base);
    *reinterpret_cast<float4*>(&sv[4]) = *reinterpret_cast<const float4*>(sem + base + 4);

    float s0 = 0.f, s1 = 0.f;
#pragma unroll
    for (int i = 0; i < 8; i++) {
        s0 += tanhf(a0[i]) * sv[i];
        s1 += tanhf(a1[i]) * sv[i];
    }
#pragma unroll
    for (int o = 16; o > 0; o >>= 1) {
        s0 += __shfl_xor_sync(0xffffffffu, s0, o);
        s1 += __shfl_xor_sync(0xffffffffu, s1, o);
    }
    float m = fmaxf(s0, s1);
    float e0 = __expf(s0 - m), e1 = __expf(s1 - m);
    float w0 = e0 / (e0 + e1);
    float w1 = 1.0f - w0;

    float f[8];
    float sum = 0.f, sq = 0.f;
#pragma unroll
    for (int i = 0; i < 8; i++) {
        f[i] = fmaxf(w0 * a0[i] + w1 * a1[i], 0.f);
        sum += f[i];
        sq  += f[i] * f[i];
    }
#pragma unroll
    for (int o = 16; o > 0; o >>= 1) {
        sum += __shfl_xor_sync(0xffffffffu, sum, o);
        sq  += __shfl_xor_sync(0xffffffffu, sq, o);
    }
    float mu  = sum * (1.0f / 256.0f);
    float var = sq * (1.0f / 256.0f) - mu * mu;
    float rstd = rsqrtf(var + LN_EPS);

    float gm[8], bt[8];
    *reinterpret_cast<float4*>(&gm[0]) = *reinterpret_cast<const float4*>(gamma + base);
    *reinterpret_cast<float4*>(&gm[4]) = *reinterpret_cast<const float4*>(gamma + base + 4);
    *reinterpret_cast<float4*>(&bt[0]) = *reinterpret_cast<const float4*>(beta + base);
    *reinterpret_cast<float4*>(&bt[4]) = *reinterpret_cast<const float4*>(beta + base + 4);

    float o8[8];
#pragma unroll
    for (int i = 0; i < 8; i++)
        o8[i] = (f[i] - mu) * rstd * gm[i] + bt[i];

    float* op = outA + (size_t)n * 256 + base;
    *reinterpret_cast<float4*>(op)     = *reinterpret_cast<float4*>(&o8[0]);
    *reinterpret_cast<float4*>(op + 4) = *reinterpret_cast<float4*>(&o8[4]);
}

// ---------------- launch ----------------------------------------------------
extern "C" void kernel_launch(void* const* d_in, const int* in_sizes, int n_in,
                              void* d_out, int out_size)
{
    const float* x_B  = (const float*)d_in[1];
    const int*   ei0  = (const int*)d_in[2];
    const int*   ei1  = (const int*)d_in[3];
    const float* W0   = (const float*)d_in[4];
    const float* b0   = (const float*)d_in[5];
    const float* W1   = (const float*)d_in[6];
    const float* b1   = (const float*)d_in[7];
    const float* sem  = (const float*)d_in[8];
    const float* gam  = (const float*)d_in[9];
    const float* bet  = (const float*)d_in[10];

    float* outA = (float*)d_out;
    float* outB = outA + (size_t)NA * OUT_DIM;

    cudaFuncSetAttribute(gemm_mma_kernel,
                         cudaFuncAttributeMaxDynamicSharedMemorySize, GSM_TOTAL);

    // 1) zero out_B + hist
    {
        size_t total = (size_t)NB * OUT_DIM / 4 + NBIN / 4;
        zero_kernel<<<(int)((total + 255) / 256), 256>>>(outB);
    }
    // 2) split + transpose W -> bf16 hi/lo
    splitW_kernel<<<512, 256>>>(W0, W1);
    // 3) CSR build: histogram -> scan -> fill
    hist_kernel<<<(2 * NE + 255) / 256, 256>>>(ei0, ei1);
    scanA_kernel<<<NBLK, SCAN_B>>>();
    scanB_kernel<<<1, SCAN_B>>>();
    scanC_kernel<<<NBLK, SCAN_B>>>();
    fill_kernel<<<(2 * NE + 255) / 256, 256>>>(ei0, ei1);
    // 4) gather-aggregate -> bf16 hi/lo sums
    agg_kernel<<<(NBIN * 32 + 255) / 256, 256>>>(x_B);
    // 5) HMMA GEMM: agg = (S @ W)/cnt + b
    {
        dim3 grid(4, (NA + 127) / 128);
        gemm_mma_kernel<<<grid, 256, GSM_TOTAL>>>(b0, b1);
    }
    // 6) semantic attention + relu + layernorm
    finalize_kernel<<<(NA * 32 + 255) / 256, 256>>>(sem, gam, bet, outA);
}

// round 6
// speedup vs baseline: 1.9713x; 1.0187x over previous
#include <cuda_runtime.h>
#include <cuda_bf16.h>
#include <cstdint>

#define NA 100000
#define NB 100000
#define IN_DIM 256
#define OUT_DIM 256
#define NE 320000
#define LN_EPS 1e-5f

#define NBIN (2 * NA)            // 200000 (p, dst) bins
#define SCAN_B 512
#define NBLK ((NBIN + SCAN_B - 1) / SCAN_B)   // 391

// ---------------- scratch (device globals; no allocation allowed) -----------
__device__ float g_agg[(size_t)2 * NA * 256];        // per-path mean+bias
__device__ float g_cnt[NBIN];
__device__ __nv_bfloat16 g_Shi[(size_t)NBIN * 256];  // aggregated sums, bf16 hi
__device__ __nv_bfloat16 g_Slo[(size_t)NBIN * 256];  // bf16 lo residual
__device__ __nv_bfloat16 g_Wt_hi[512 * 256];         // Wcat^T [n][k]
__device__ __nv_bfloat16 g_Wt_lo[512 * 256];
__device__ int g_hist[NBIN];
__device__ int g_rowptr[NBIN];
__device__ int g_cursor[NBIN];
__device__ int g_elist[2 * NE];
__device__ int g_blocksums[SCAN_B];
__device__ int g_blockoff[SCAN_B];

// ---------------- helpers ----------------------------------------------------
__device__ __forceinline__ uint32_t smem_u32(const void* p) {
    uint32_t a;
    asm("{ .reg .u64 t; cvta.to.shared.u64 t, %1; cvt.u32.u64 %0, t; }" : "=r"(a) : "l"(p));
    return a;
}
__device__ __forceinline__ void ldsm_x4(uint32_t& r0, uint32_t& r1, uint32_t& r2,
                                        uint32_t& r3, uint32_t addr) {
    asm volatile("ldmatrix.sync.aligned.m8n8.x4.shared.b16 {%0,%1,%2,%3}, [%4];"
                 : "=r"(r0), "=r"(r1), "=r"(r2), "=r"(r3) : "r"(addr));
}
__device__ __forceinline__ void mma_bf16(float* c, const uint32_t* a, const uint32_t* b) {
    asm volatile("mma.sync.aligned.m16n8k16.row.col.f32.bf16.bf16.f32 "
                 "{%0,%1,%2,%3}, {%4,%5,%6,%7}, {%8,%9}, {%0,%1,%2,%3};"
                 : "+f"(c[0]), "+f"(c[1]), "+f"(c[2]), "+f"(c[3])
                 : "r"(a[0]), "r"(a[1]), "r"(a[2]), "r"(a[3]), "r"(b[0]), "r"(b[1]));
}
#define CP_ASYNC16(sm, gp) \
    asm volatile("cp.async.cg.shared.global [%0], [%1], 16;" \
                 :: "r"(sm), "l"(gp) : "memory")
#define CP_ASYNC16Z(sm, gp, sz) \
    asm volatile("cp.async.cg.shared.global [%0], [%1], 16, %2;" \
                 :: "r"(sm), "l"(gp), "r"(sz) : "memory")
#define CP_COMMIT() asm volatile("cp.async.commit_group;" ::: "memory")
#define CP_WAIT0()  asm volatile("cp.async.wait_group 0;" ::: "memory")
#define CP_WAIT1()  asm volatile("cp.async.wait_group 1;" ::: "memory")
#define CP_WAIT2()  asm volatile("cp.async.wait_group 2;" ::: "memory")

// ---------------- zero: out_B + hist -----------------------------------------
__global__ __launch_bounds__(256) void zero_kernel(float* __restrict__ outB) {
    size_t i = (size_t)blockIdx.x * 256 + threadIdx.x;
    const size_t n4_outB = (size_t)NB * OUT_DIM / 4;   // 6,400,000
    const size_t n4_hist = NBIN / 4;                   // 50,000
    if (i < n4_outB) {
        reinterpret_cast<float4*>(outB)[i] = make_float4(0.f, 0.f, 0.f, 0.f);
    } else if (i < n4_outB + n4_hist) {
        reinterpret_cast<int4*>(g_hist)[i - n4_outB] = make_int4(0, 0, 0, 0);
    }
}

// ---------------- W split/transpose prep ------------------------------------
__global__ __launch_bounds__(256) void splitW_kernel(const float* __restrict__ W0,
                                                     const float* __restrict__ W1) {
    int n = blockIdx.x;
    int k = threadIdx.x;
    float w = (n < 256) ? W0[k * 256 + n] : W1[k * 256 + (n - 256)];
    __nv_bfloat16 h = __float2bfloat16_rn(w);
    float r = w - __bfloat162float(h);
    g_Wt_hi[n * 256 + k] = h;
    g_Wt_lo[n * 256 + k] = __float2bfloat16_rn(r);
}

// ---------------- CSR build --------------------------------------------------
__global__ __launch_bounds__(256) void hist_kernel(
    const int* __restrict__ ei0, const int* __restrict__ ei1)
{
    int i = blockIdx.x * 256 + threadIdx.x;
    if (i >= 2 * NE) return;
    int p = (i >= NE) ? 1 : 0;
    int e = i - p * NE;
    const int* __restrict__ ei = p ? ei1 : ei0;
    int dst = ei[e + NE];
    atomicAdd(&g_hist[p * NA + dst], 1);
}

__global__ __launch_bounds__(SCAN_B) void scanA_kernel() {
    __shared__ int sh[SCAN_B];
    int i = blockIdx.x * SCAN_B + threadIdx.x;
    sh[threadIdx.x] = (i < NBIN) ? g_hist[i] : 0;
    __syncthreads();
    for (int d = SCAN_B / 2; d > 0; d >>= 1) {
        if (threadIdx.x < d) sh[threadIdx.x] += sh[threadIdx.x + d];
        __syncthreads();
    }
    if (threadIdx.x == 0) g_blocksums[blockIdx.x] = sh[0];
}

__global__ __launch_bounds__(SCAN_B) void scanB_kernel() {
    __shared__ int sh[SCAN_B];
    int tid = threadIdx.x;
    int v = (tid < NBLK) ? g_blocksums[tid] : 0;
    sh[tid] = v;
    __syncthreads();
    for (int d = 1; d < SCAN_B; d <<= 1) {
        int t = (tid >= d) ? sh[tid - d] : 0;
        __syncthreads();
        sh[tid] += t;
        __syncthreads();
    }
    if (tid < NBLK) g_blockoff[tid] = sh[tid] - v;   // exclusive
}

__global__ __launch_bounds__(SCAN_B) void scanC_kernel() {
    __shared__ int sh[SCAN_B];
    int tid = threadIdx.x;
    int i = blockIdx.x * SCAN_B + tid;
    int v = (i < NBIN) ? g_hist[i] : 0;
    sh[tid] = v;
    __syncthreads();
    for (int d = 1; d < SCAN_B; d <<= 1) {
        int t = (tid >= d) ? sh[tid - d] : 0;
        __syncthreads();
        sh[tid] += t;
        __syncthreads();
    }
    if (i < NBIN) {
        int excl = sh[tid] - v + g_blockoff[blockIdx.x];
        g_rowptr[i] = excl;
        g_cursor[i] = excl;
        g_cnt[i] = (float)v;
    }
}

__global__ __launch_bounds__(256) void fill_kernel(
    const int* __restrict__ ei0, const int* __restrict__ ei1)
{
    int i = blockIdx.x * 256 + threadIdx.x;
    if (i >= 2 * NE) return;
    int p = (i >= NE) ? 1 : 0;
    int e = i - p * NE;
    const int* __restrict__ ei = p ? ei1 : ei0;
    int src = ei[e];
    int dst = ei[e + NE];
    int pos = atomicAdd(&g_cursor[p * NA + dst], 1);
    g_elist[pos] = src;
}

// ---------------- aggregate: warp per (p, dst); output bf16 hi/lo ------------
// Unrolled x4: batch 8 independent LDG.128 before accumulating (MLP ~8).
__global__ __launch_bounds__(256) void agg_kernel(const float* __restrict__ xB) {
    int w = (blockIdx.x * 256 + threadIdx.x) >> 5;
    int lane = threadIdx.x & 31;
    if (w >= NBIN) return;
    int start = g_rowptr[w];
    int deg = g_hist[w];

    float a[8] = {0.f, 0.f, 0.f, 0.f, 0.f, 0.f, 0.f, 0.f};

    int j = 0;
    for (; j + 4 <= deg; j += 4) {
        int4 s4 = *reinterpret_cast<const int4*>(&g_elist[start + j]);  // start 4-aligned? no — use scalar
        // NOTE: start is not 4-aligned in general; load scalars instead.
        (void)s4;
        break;
    }
    // scalar-index, batched-data version (indices via 4 scalar loads, data 8x LDG.128)
    j = 0;
    for (; j + 4 <= deg; j += 4) {
        int s0 = __ldg(&g_elist[start + j]);
        int s1 = __ldg(&g_elist[start + j + 1]);
        int s2 = __ldg(&g_elist[start + j + 2]);
        int s3 = __ldg(&g_elist[start + j + 3]);
        const float4* r0 = reinterpret_cast<const float4*>(xB + (size_t)s0 * 256) + lane * 2;
        const float4* r1 = reinterpret_cast<const float4*>(xB + (size_t)s1 * 256) + lane * 2;
        const float4* r2 = reinterpret_cast<const float4*>(xB + (size_t)s2 * 256) + lane * 2;
        const float4* r3 = reinterpret_cast<const float4*>(xB + (size_t)s3 * 256) + lane * 2;
        float4 v0a = r0[0], v0b = r0[1];
        float4 v1a = r1[0], v1b = r1[1];
        float4 v2a = r2[0], v2b = r2[1];
        float4 v3a = r3[0], v3b = r3[1];
        a[0] += v0a.x + v1a.x + v2a.x + v3a.x;
        a[1] += v0a.y + v1a.y + v2a.y + v3a.y;
        a[2] += v0a.z + v1a.z + v2a.z + v3a.z;
        a[3] += v0a.w + v1a.w + v2a.w + v3a.w;
        a[4] += v0b.x + v1b.x + v2b.x + v3b.x;
        a[5] += v0b.y + v1b.y + v2b.y + v3b.y;
        a[6] += v0b.z + v1b.z + v2b.z + v3b.z;
        a[7] += v0b.w + v1b.w + v2b.w + v3b.w;
    }
    for (; j < deg; j++) {
        int src = __ldg(&g_elist[start + j]);
        const float4* r4 = reinterpret_cast<const float4*>(xB + (size_t)src * 256) + lane * 2;
        float4 v0 = r4[0], v1 = r4[1];
        a[0] += v0.x; a[1] += v0.y; a[2] += v0.z; a[3] += v0.w;
        a[4] += v1.x; a[5] += v1.y; a[6] += v1.z; a[7] += v1.w;
    }

    uint4 hv, lv;
    {
        __nv_bfloat162 h0 = __floats2bfloat162_rn(a[0], a[1]);
        __nv_bfloat162 h1 = __floats2bfloat162_rn(a[2], a[3]);
        __nv_bfloat162 h2 = __floats2bfloat162_rn(a[4], a[5]);
        __nv_bfloat162 h3 = __floats2bfloat162_rn(a[6], a[7]);
        __nv_bfloat162 l0 = __floats2bfloat162_rn(a[0] - __bfloat162float(h0.x),
                                                  a[1] - __bfloat162float(h0.y));
        __nv_bfloat162 l1 = __floats2bfloat162_rn(a[2] - __bfloat162float(h1.x),
                                                  a[3] - __bfloat162float(h1.y));
        __nv_bfloat162 l2 = __floats2bfloat162_rn(a[4] - __bfloat162float(h2.x),
                                                  a[5] - __bfloat162float(h2.y));
        __nv_bfloat162 l3 = __floats2bfloat162_rn(a[6] - __bfloat162float(h3.x),
                                                  a[7] - __bfloat162float(h3.y));
        hv.x = *reinterpret_cast<uint32_t*>(&h0); hv.y = *reinterpret_cast<uint32_t*>(&h1);
        hv.z = *reinterpret_cast<uint32_t*>(&h2); hv.w = *reinterpret_cast<uint32_t*>(&h3);
        lv.x = *reinterpret_cast<uint32_t*>(&l0); lv.y = *reinterpret_cast<uint32_t*>(&l1);
        lv.z = *reinterpret_cast<uint32_t*>(&l2); lv.w = *reinterpret_cast<uint32_t*>(&l3);
    }
    *reinterpret_cast<uint4*>(g_Shi + (size_t)w * 256 + lane * 8) = hv;
    *reinterpret_cast<uint4*>(g_Slo + (size_t)w * 256 + lane * 8) = lv;
}

// ---------------- HMMA GEMM: agg = (S @ W)/cnt + b --------------------------
// grid (4, 782): bx = p*2+h (fast -> A-tile L2 reuse), by = m-tile.
// K-chunk 32, 3-stage cp.async pipeline. Stage = [A 16KB | B 16KB] = 32KB.
#define GBUF 32768
#define GSM_TOTAL (3 * GBUF)

__device__ __forceinline__ void gemm_issue(
    uint32_t sb, int tid, int m0,
    const __nv_bfloat16* __restrict__ Ahi, const __nv_bfloat16* __restrict__ Alo,
    const __nv_bfloat16* __restrict__ Bhi, const __nv_bfloat16* __restrict__ Blo,
    int kc)
{
#pragma unroll
    for (int l = 0; l < 4; l++) {
        int ulin = l * 256 + tid;
        int r = ulin >> 3, u = ulin & 7;
        int grow = m0 + r;
        int ok = (grow < NA) ? 16 : 0;
        int grc = (grow < NA) ? grow : (NA - 1);
        uint32_t dst = sb + (uint32_t)(r * 128 + ((u ^ (r & 7)) << 4));
        const __nv_bfloat16* src = (u < 4)
            ? (Ahi + (size_t)grc * 256 + kc * 32 + (u & 3) * 8)
            : (Alo + (size_t)grc * 256 + kc * 32 + (u & 3) * 8);
        CP_ASYNC16Z(dst, src, ok);
    }
#pragma unroll
    for (int l = 0; l < 4; l++) {
        int ulin = l * 256 + tid;
        int n = ulin >> 3, u = ulin & 7;
        uint32_t dst = sb + 16384u + (uint32_t)(n * 128 + ((u ^ (n & 7)) << 4));
        const __nv_bfloat16* src = (u < 4)
            ? (Bhi + (size_t)n * 256 + kc * 32 + (u & 3) * 8)
            : (Blo + (size_t)n * 256 + kc * 32 + (u & 3) * 8);
        CP_ASYNC16(dst, src);
    }
    CP_COMMIT();
}

__global__ __launch_bounds__(256, 2) void gemm_mma_kernel(
    const float* __restrict__ b0, const float* __restrict__ b1)
{
    extern __shared__ char smem[];
    const uint32_t sbase = smem_u32(smem);
    const int tid = threadIdx.x, lane = tid & 31, wid = tid >> 5;
    const int wm = wid & 3;
    const int wn = wid >> 2;
    const int p = blockIdx.x >> 1, h = blockIdx.x & 1;
    const int m0 = blockIdx.y * 128;

    const __nv_bfloat16* __restrict__ Ahi = g_Shi + (size_t)p * NA * 256;
    const __nv_bfloat16* __restrict__ Alo = g_Slo + (size_t)p * NA * 256;
    const __nv_bfloat16* __restrict__ Bhi = g_Wt_hi + (size_t)(p * 256 + h * 128) * 256;
    const __nv_bfloat16* __restrict__ Blo = g_Wt_lo + (size_t)(p * 256 + h * 128) * 256;

    float c[2][8][4];
#pragma unroll
    for (int mt = 0; mt < 2; mt++)
#pragma unroll
        for (int n8 = 0; n8 < 8; n8++)
#pragma unroll
            for (int q = 0; q < 4; q++) c[mt][n8][q] = 0.f;

    const int am = lane & 15;
    const int aoff = lane >> 4;
    const int asw = am & 7;
    const int bn = (lane & 7) | ((lane & 16) >> 1);
    const int boff = (lane >> 3) & 1;
    const int bsw = bn & 7;

    gemm_issue(sbase, tid, m0, Ahi, Alo, Bhi, Blo, 0);
    gemm_issue(sbase + GBUF, tid, m0, Ahi, Alo, Bhi, Blo, 1);

    for (int kc = 0; kc < 8; kc++) {
        if (kc + 2 < 8) {
            gemm_issue(sbase + ((kc + 2) % 3) * GBUF, tid, m0, Ahi, Alo, Bhi, Blo, kc + 2);
            CP_WAIT2();
        } else if (kc + 1 < 8) {
            CP_WAIT1();
        } else {
            CP_WAIT0();
        }
        __syncthreads();
        const uint32_t sb = sbase + (kc % 3) * GBUF;

#pragma unroll
        for (int s = 0; s < 2; s++) {
            const int uhi = (s << 1) | aoff;
            uint32_t ah[2][4], al[2][4];
#pragma unroll
            for (int mt = 0; mt < 2; mt++) {
                int arow = wm * 32 + mt * 16 + am;
                uint32_t rb = sb + (uint32_t)(arow * 128);
                ldsm_x4(ah[mt][0], ah[mt][1], ah[mt][2], ah[mt][3],
                        rb + ((uhi ^ asw) << 4));
                ldsm_x4(al[mt][0], al[mt][1], al[mt][2], al[mt][3],
                        rb + (((4 | uhi) ^ asw) << 4));
            }
            const int vhi = (s << 1) | boff;
#pragma unroll
            for (int g = 0; g < 4; g++) {
                int brow = wn * 64 + g * 16 + bn;
                uint32_t rb = sb + 16384u + (uint32_t)(brow * 128);
                uint32_t bh[4], bl[4];
                ldsm_x4(bh[0], bh[1], bh[2], bh[3], rb + ((vhi ^ bsw) << 4));
                ldsm_x4(bl[0], bl[1], bl[2], bl[3], rb + (((4 | vhi) ^ bsw) << 4));
#pragma unroll
                for (int mt = 0; mt < 2; mt++) {
                    mma_bf16(c[mt][2 * g],     ah[mt], &bh[0]);
                    mma_bf16(c[mt][2 * g],     ah[mt], &bl[0]);
                    mma_bf16(c[mt][2 * g],     al[mt], &bh[0]);
                    mma_bf16(c[mt][2 * g + 1], ah[mt], &bh[2]);
                    mma_bf16(c[mt][2 * g + 1], ah[mt], &bl[2]);
                    mma_bf16(c[mt][2 * g + 1], al[mt], &bh[2]);
                }
            }
        }
        __syncthreads();
    }

    // ---- epilogue: mean + bias -> g_agg ------------------------------------
    const float* __restrict__ bias = p ? b1 : b0;
    float* __restrict__ dst = g_agg + (size_t)p * NA * 256;
#pragma unroll
    for (int mt = 0; mt < 2; mt++) {
#pragma unroll
        for (int rr = 0; rr < 2; rr++) {
            int row = m0 + wm * 32 + mt * 16 + rr * 8 + (lane >> 2);
            if (row >= NA) continue;
            float cv = g_cnt[p * NA + row];
            float inv = cv > 0.f ? 1.f / cv : 0.f;
            float bf = cv > 0.f ? 1.f : 0.f;
            float* orow = dst + (size_t)row * 256;
#pragma unroll
            for (int n8 = 0; n8 < 8; n8++) {
                int col = h * 128 + wn * 64 + n8 * 8 + (lane & 3) * 2;
                float2 o;
                o.x = c[mt][n8][rr * 2 + 0] * inv + bias[col] * bf;
                o.y = c[mt][n8][rr * 2 + 1] * inv + bias[col + 1] * bf;
                *reinterpret_cast<float2*>(orow + col) = o;
            }
        }
    }
}

// ---------------- finalize: one warp per destination row --------------------
__global__ __launch_bounds__(256) void finalize_kernel(
    const float* __restrict__ sem, const float* __restrict__ gamma,
    const float* __restrict__ beta, float* __restrict__ outA)
{
    int n = (blockIdx.x * 256 + threadIdx.x) >> 5;
    int lane = threadIdx.x & 31;
    if (n >= NA) return;
    int base = lane * 8;

    const float* a0p = g_agg + (size_t)n * 256;
    const float* a1p = g_agg + ((size_t)NA + n) * 256;

    float a0[8], a1[8], sv[8];
    *reinterpret_cast<float4*>(&a0[0]) = *reinterpret_cast<const float4*>(a0p + base);
    *reinterpret_cast<float4*>(&a0[4]) = *reinterpret_cast<const float4*>(a0p + base + 4);
    *reinterpret_cast<float4*>(&a1[0]) = *reinterpret_cast<const float4*>(a1p + base);
    *reinterpret_cast<float4*>(&a1[4]) = *reinterpret_cast<const float4*>(a1p + base + 4);
    *reinterpret_cast<float4*>(&sv[0]) = *reinterpret_cast<const float4*>(sem + base);
    *reinterpret_cast<float4*>(&sv[4]) = *reinterpret_cast<const float4*>(sem + base + 4);

    float s0 = 0.f, s1 = 0.f;
#pragma unroll
    for (int i = 0; i < 8; i++) {
        s0 += tanhf(a0[i]) * sv[i];
        s1 += tanhf(a1[i]) * sv[i];
    }
#pragma unroll
    for (int o = 16; o > 0; o >>= 1) {
        s0 += __shfl_xor_sync(0xffffffffu, s0, o);
        s1 += __shfl_xor_sync(0xffffffffu, s1, o);
    }
    float m = fmaxf(s0, s1);
    float e0 = __expf(s0 - m), e1 = __expf(s1 - m);
    float w0 = e0 / (e0 + e1);
    float w1 = 1.0f - w0;

    float f[8];
    float sum = 0.f, sq = 0.f;
#pragma unroll
    for (int i = 0; i < 8; i++) {
        f[i] = fmaxf(w0 * a0[i] + w1 * a1[i], 0.f);
        sum += f[i];
        sq  += f[i] * f[i];
    }
#pragma unroll
    for (int o = 16; o > 0; o >>= 1) {
        sum += __shfl_xor_sync(0xffffffffu, sum, o);
        sq  += __shfl_xor_sync(0xffffffffu, sq, o);
    }
    float mu  = sum * (1.0f / 256.0f);
    float var = sq * (1.0f / 256.0f) - mu * mu;
    float rstd = rsqrtf(var + LN_EPS);

    float gm[8], bt[8];
    *reinterpret_cast<float4*>(&gm[0]) = *reinterpret_cast<const float4*>(gamma + base);
    *reinterpret_cast<float4*>(&gm[4]) = *reinterpret_cast<const float4*>(gamma + base + 4);
    *reinterpret_cast<float4*>(&bt[0]) = *reinterpret_cast<const float4*>(beta + base);
    *reinterpret_cast<float4*>(&bt[4]) = *reinterpret_cast<const float4*>(beta + base + 4);

    float o8[8];
#pragma unroll
    for (int i = 0; i < 8; i++)
        o8[i] = (f[i] - mu) * rstd * gm[i] + bt[i];

    float* op = outA + (size_t)n * 256 + base;
    *reinterpret_cast<float4*>(op)     = *reinterpret_cast<float4*>(&o8[0]);
    *reinterpret_cast<float4*>(op + 4) = *reinterpret_cast<float4*>(&o8[4]);
}

// ---------------- launch ----------------------------------------------------
extern "C" void kernel_launch(void* const* d_in, const int* in_sizes, int n_in,
                              void* d_out, int out_size)
{
    const float* x_B  = (const float*)d_in[1];
    const int*   ei0  = (const int*)d_in[2];
    const int*   ei1  = (const int*)d_in[3];
    const float* W0   = (const float*)d_in[4];
    const float* b0   = (const float*)d_in[5];
    const float* W1   = (const float*)d_in[6];
    const float* b1   = (const float*)d_in[7];
    const float* sem  = (const float*)d_in[8];
    const float* gam  = (const float*)d_in[9];
    const float* bet  = (const float*)d_in[10];

    float* outA = (float*)d_out;
    float* outB = outA + (size_t)NA * OUT_DIM;

    cudaFuncSetAttribute(gemm_mma_kernel,
                         cudaFuncAttributeMaxDynamicSharedMemorySize, GSM_TOTAL);

    // 1) zero out_B + hist
    {
        size_t total = (size_t)NB * OUT_DIM / 4 + NBIN / 4;
        zero_kernel<<<(int)((total + 255) / 256), 256>>>(outB);
    }
    // 2) split + transpose W -> bf16 hi/lo
    splitW_kernel<<<512, 256>>>(W0, W1);
    // 3) CSR build: histogram -> scan -> fill
    hist_kernel<<<(2 * NE + 255) / 256, 256>>>(ei0, ei1);
    scanA_kernel<<<NBLK, SCAN_B>>>();
    scanB_kernel<<<1, SCAN_B>>>();
    scanC_kernel<<<NBLK, SCAN_B>>>();
    fill_kernel<<<(2 * NE + 255) / 256, 256>>>(ei0, ei1);
    // 4) gather-aggregate -> bf16 hi/lo sums
    agg_kernel<<<(NBIN * 32 + 255) / 256, 256>>>(x_B);
    // 5) HMMA GEMM: agg = (S @ W)/cnt + b
    {
        dim3 grid(4, (NA + 127) / 128);
        gemm_mma_kernel<<<grid, 256, GSM_TOTAL>>>(b0, b1);
    }
    // 6) semantic attention + relu + layernorm
    finalize_kernel<<<(NA * 32 + 255) / 256, 256>>>(sem, gam, bet, outA);
}